// round 1
// baseline (speedup 1.0000x reference)
#include <cuda_runtime.h>
#include <cuda_bf16.h>
#include <math.h>

#define NTOK 2048
#define DMODEL 1024
#define NHEAD 16
#define NKV 4
#define HEADDIM 64
#define FFN 4096
#define VOCAB 32000
#define NLAYER 4
#define SEQ 1024
#define KVDIM (NKV * HEADDIM)   // 256

// ---------------- scratch (device globals; no runtime allocation) ----------------
__device__ float g_x[NTOK * DMODEL];
__device__ float g_h[NTOK * DMODEL];
__device__ float g_q[NTOK * DMODEL];
__device__ float g_k[NTOK * KVDIM];
__device__ float g_v[NTOK * KVDIM];
__device__ float g_o[NTOK * DMODEL];
__device__ float g_gate[NTOK * FFN];
__device__ float g_up[NTOK * FFN];

// ---------------- embedding gather ----------------
__global__ void embed_kernel(const int* __restrict__ ids,
                             const float* __restrict__ emb,
                             float* __restrict__ x) {
    int idx = blockIdx.x * 256 + threadIdx.x;   // over NTOK*256 float4s
    int n = idx >> 8;
    int c = idx & 255;
    const float4* e4 = (const float4*)emb;
    ((float4*)x)[idx] = e4[(size_t)ids[n] * 256 + c];
}

// ---------------- RMSNorm (one block per token) ----------------
__global__ void rmsnorm_kernel(const float* __restrict__ x,
                               const float* __restrict__ w,
                               float* __restrict__ out) {
    int n = blockIdx.x;
    int tid = threadIdx.x;
    const float4* xr = (const float4*)(x + (size_t)n * DMODEL);
    float4 v = xr[tid];
    float ss = v.x * v.x + v.y * v.y + v.z * v.z + v.w * v.w;
#pragma unroll
    for (int o = 16; o > 0; o >>= 1) ss += __shfl_xor_sync(0xffffffffu, ss, o);
    __shared__ float red[8];
    if ((tid & 31) == 0) red[tid >> 5] = ss;
    __syncthreads();
    float tot = 0.f;
#pragma unroll
    for (int i = 0; i < 8; i++) tot += red[i];
    float r = rsqrtf(tot * (1.0f / DMODEL) + 1e-6f);
    float4 wv = ((const float4*)w)[tid];
    float4 ov;
    ov.x = wv.x * v.x * r;
    ov.y = wv.y * v.y * r;
    ov.z = wv.z * v.z * r;
    ov.w = wv.w * v.w * r;
    ((float4*)(out + (size_t)n * DMODEL))[tid] = ov;
}

// ---------------- RoPE (in-place) ----------------
__global__ void rope_kernel(float* __restrict__ buf, int nheads) {
    int idx = blockIdx.x * blockDim.x + threadIdx.x;
    int i = idx & 31;                // rotary pair index 0..31
    int hn = idx >> 5;               // token*nheads + head
    int head = hn % nheads;
    int n = hn / nheads;
    int t = n & (SEQ - 1);           // position within sequence
    float inv = 1.0f / powf(10000.0f, (float)i * (1.0f / 32.0f));
    float ang = (float)t * inv;
    float s, c;
    sincosf(ang, &s, &c);
    float* p = buf + (size_t)n * nheads * HEADDIM + head * HEADDIM + i;
    float x1 = p[0], x2 = p[32];
    p[0]  = x1 * c - x2 * s;
    p[32] = x2 * c + x1 * s;
}

// ---------------- SGEMM: C[N,M] = A[N,K] * W[M,K]^T (+ epilogue) ----------------
// EPI: 0 = store, 1 = residual add (aux = residual), 2 = SiLU, 3 = mul by aux
template <int EPI>
__global__ __launch_bounds__(256) void sgemm_kernel(
    const float* __restrict__ A, const float* __restrict__ W,
    float* __restrict__ C, const float* __restrict__ aux,
    int N, int M, int K) {
    __shared__ float As[16][128];
    __shared__ float Ws[16][128];
    int tid = threadIdx.x;
    int m0 = blockIdx.x * 128;
    int n0 = blockIdx.y * 128;
    int tx = tid & 15, ty = tid >> 4;
    float acc[8][8] = {};
    const float* Ag = A + (size_t)n0 * K;
    const float* Wg = W + (size_t)m0 * K;
    int arow0 = tid >> 2;
    int ac4 = (tid & 3) * 4;
    for (int kt = 0; kt < K; kt += 16) {
#pragma unroll
        for (int i = 0; i < 2; i++) {
            int row = arow0 + i * 64;
            float4 av = *(const float4*)(Ag + (size_t)row * K + kt + ac4);
            As[ac4 + 0][row] = av.x;
            As[ac4 + 1][row] = av.y;
            As[ac4 + 2][row] = av.z;
            As[ac4 + 3][row] = av.w;
            float4 wv = *(const float4*)(Wg + (size_t)row * K + kt + ac4);
            Ws[ac4 + 0][row] = wv.x;
            Ws[ac4 + 1][row] = wv.y;
            Ws[ac4 + 2][row] = wv.z;
            Ws[ac4 + 3][row] = wv.w;
        }
        __syncthreads();
#pragma unroll
        for (int kk = 0; kk < 16; kk++) {
            float4 a0 = *(const float4*)&As[kk][ty * 8];
            float4 a1 = *(const float4*)&As[kk][ty * 8 + 4];
            float4 b0 = *(const float4*)&Ws[kk][tx * 8];
            float4 b1 = *(const float4*)&Ws[kk][tx * 8 + 4];
            float a[8] = {a0.x, a0.y, a0.z, a0.w, a1.x, a1.y, a1.z, a1.w};
            float b[8] = {b0.x, b0.y, b0.z, b0.w, b1.x, b1.y, b1.z, b1.w};
#pragma unroll
            for (int i = 0; i < 8; i++)
#pragma unroll
                for (int j = 0; j < 8; j++) acc[i][j] += a[i] * b[j];
        }
        __syncthreads();
    }
#pragma unroll
    for (int i = 0; i < 8; i++) {
        int n = n0 + ty * 8 + i;
        float* crow = C + (size_t)n * M + m0 + tx * 8;
        const float* arow = aux + (size_t)n * M + m0 + tx * 8;
#pragma unroll
        for (int j4 = 0; j4 < 2; j4++) {
            float4 r;
            r.x = acc[i][j4 * 4 + 0];
            r.y = acc[i][j4 * 4 + 1];
            r.z = acc[i][j4 * 4 + 2];
            r.w = acc[i][j4 * 4 + 3];
            if (EPI == 1) {
                float4 rv = *(const float4*)(arow + j4 * 4);
                r.x += rv.x; r.y += rv.y; r.z += rv.z; r.w += rv.w;
            } else if (EPI == 2) {
                r.x = r.x / (1.0f + __expf(-r.x));
                r.y = r.y / (1.0f + __expf(-r.y));
                r.z = r.z / (1.0f + __expf(-r.z));
                r.w = r.w / (1.0f + __expf(-r.w));
            } else if (EPI == 3) {
                float4 rv = *(const float4*)(arow + j4 * 4);
                r.x *= rv.x; r.y *= rv.y; r.z *= rv.z; r.w *= rv.w;
            }
            *(float4*)(crow + j4 * 4) = r;
        }
    }
}

// ---------------- causal flash attention (fp32, GQA) ----------------
// grid: (SEQ/64, B*NHEAD), block: 256 (8 warps x 8 query rows each)
__global__ __launch_bounds__(256) void attn_kernel(
    const float* __restrict__ Q, const float* __restrict__ K,
    const float* __restrict__ V, float* __restrict__ O) {
    __shared__ float Qs[64][64];
    __shared__ float Ks[32][68];   // pad 68: conflict-free lane-major float4 reads
    __shared__ float Vs[32][64];
    __shared__ float Ps[64][33];
    int bh = blockIdx.y;
    int b = bh >> 4;           // / NHEAD
    int h = bh & 15;           // % NHEAD
    int kvh = h >> 2;          // GQA group: head h -> kv head h/4
    int q0 = blockIdx.x * 64;
    int tid = threadIdx.x;
    int lane = tid & 31, warp = tid >> 5;
    const float scale = 0.125f;  // 1/sqrt(64)

    const float* Qbase = Q + ((size_t)(b * SEQ + q0)) * DMODEL + h * HEADDIM;
    for (int i = tid; i < 64 * 16; i += 256) {
        int row = i >> 4, c = (i & 15) * 4;
        float4 v = *(const float4*)(Qbase + (size_t)row * DMODEL + c);
        Qs[row][c + 0] = v.x * scale;
        Qs[row][c + 1] = v.y * scale;
        Qs[row][c + 2] = v.z * scale;
        Qs[row][c + 3] = v.w * scale;
    }

    float m[8], l[8], acc0[8], acc1[8];
#pragma unroll
    for (int r = 0; r < 8; r++) { m[r] = -1e30f; l[r] = 0.f; acc0[r] = 0.f; acc1[r] = 0.f; }

    int kend = q0 + 64;
    for (int kc = 0; kc < kend; kc += 32) {
        __syncthreads();
        const float* Kbase = K + ((size_t)(b * SEQ + kc)) * KVDIM + kvh * HEADDIM;
        const float* Vbase = V + ((size_t)(b * SEQ + kc)) * KVDIM + kvh * HEADDIM;
        for (int i = tid; i < 32 * 16; i += 256) {
            int row = i >> 4, c = (i & 15) * 4;
            float4 kv = *(const float4*)(Kbase + (size_t)row * KVDIM + c);
            Ks[row][c + 0] = kv.x;
            Ks[row][c + 1] = kv.y;
            Ks[row][c + 2] = kv.z;
            Ks[row][c + 3] = kv.w;
            float4 vv = *(const float4*)(Vbase + (size_t)row * KVDIM + c);
            *(float4*)&Vs[row][c] = vv;
        }
        __syncthreads();

        // scores: lane owns key (kc+lane), 8 query rows per warp
        float s[8] = {0.f, 0.f, 0.f, 0.f, 0.f, 0.f, 0.f, 0.f};
#pragma unroll
        for (int d4 = 0; d4 < 16; d4++) {
            float4 kv = *(const float4*)&Ks[lane][d4 * 4];
#pragma unroll
            for (int r = 0; r < 8; r++) {
                float4 qv = *(const float4*)&Qs[warp * 8 + r][d4 * 4];
                s[r] += qv.x * kv.x + qv.y * kv.y + qv.z * kv.z + qv.w * kv.w;
            }
        }
        int key = kc + lane;
#pragma unroll
        for (int r = 0; r < 8; r++) {
            int qrow = q0 + warp * 8 + r;
            float sv = (key <= qrow) ? s[r] : -1e30f;
            float mx = sv;
#pragma unroll
            for (int o = 16; o > 0; o >>= 1) mx = fmaxf(mx, __shfl_xor_sync(0xffffffffu, mx, o));
            float mn = fmaxf(m[r], mx);
            float p = __expf(sv - mn);
            float cor = __expf(m[r] - mn);
            float ps = p;
#pragma unroll
            for (int o = 16; o > 0; o >>= 1) ps += __shfl_xor_sync(0xffffffffu, ps, o);
            l[r] = l[r] * cor + ps;
            acc0[r] *= cor;
            acc1[r] *= cor;
            m[r] = mn;
            Ps[warp * 8 + r][lane] = p;
        }
        __syncwarp();
        // AV accumulate: lane owns dims (lane, lane+32)
#pragma unroll 4
        for (int j = 0; j < 32; j++) {
            float v0 = Vs[j][lane];
            float v1 = Vs[j][lane + 32];
#pragma unroll
            for (int r = 0; r < 8; r++) {
                float p = Ps[warp * 8 + r][j];
                acc0[r] += p * v0;
                acc1[r] += p * v1;
            }
        }
    }

    float* Obase = O + ((size_t)(b * SEQ + q0)) * DMODEL + h * HEADDIM;
#pragma unroll
    for (int r = 0; r < 8; r++) {
        int row = warp * 8 + r;
        float inv = 1.0f / l[r];
        Obase[(size_t)row * DMODEL + lane] = acc0[r] * inv;
        Obase[(size_t)row * DMODEL + lane + 32] = acc1[r] * inv;
    }
}

// ---------------- host orchestration ----------------
extern "C" void kernel_launch(void* const* d_in, const int* in_sizes, int n_in,
                              void* d_out, int out_size) {
    const int*   ids = (const int*)d_in[0];
    const float* emb = (const float*)d_in[1];
    const float* ln1 = (const float*)d_in[2];
    const float* qw  = (const float*)d_in[3];
    const float* kw  = (const float*)d_in[4];
    const float* vw  = (const float*)d_in[5];
    const float* ow  = (const float*)d_in[6];
    const float* ln2 = (const float*)d_in[7];
    const float* w1  = (const float*)d_in[8];
    const float* w2  = (const float*)d_in[9];
    const float* w3  = (const float*)d_in[10];
    const float* lnf = (const float*)d_in[11];
    float* out = (float*)d_out;

    float *x, *h, *q, *k, *v, *o, *gate, *up;
    cudaGetSymbolAddress((void**)&x, g_x);
    cudaGetSymbolAddress((void**)&h, g_h);
    cudaGetSymbolAddress((void**)&q, g_q);
    cudaGetSymbolAddress((void**)&k, g_k);
    cudaGetSymbolAddress((void**)&v, g_v);
    cudaGetSymbolAddress((void**)&o, g_o);
    cudaGetSymbolAddress((void**)&gate, g_gate);
    cudaGetSymbolAddress((void**)&up, g_up);

    embed_kernel<<<NTOK, 256>>>(ids, emb, x);

    for (int l = 0; l < NLAYER; l++) {
        const float* lqw = qw + (size_t)l * DMODEL * DMODEL;
        const float* lkw = kw + (size_t)l * KVDIM * DMODEL;
        const float* lvw = vw + (size_t)l * KVDIM * DMODEL;
        const float* low = ow + (size_t)l * DMODEL * DMODEL;
        const float* lw1 = w1 + (size_t)l * FFN * DMODEL;
        const float* lw2 = w2 + (size_t)l * DMODEL * FFN;
        const float* lw3 = w3 + (size_t)l * FFN * DMODEL;

        rmsnorm_kernel<<<NTOK, 256>>>(x, ln1 + l * DMODEL, h);
        sgemm_kernel<0><<<dim3(DMODEL / 128, NTOK / 128), 256>>>(h, lqw, q, nullptr, NTOK, DMODEL, DMODEL);
        sgemm_kernel<0><<<dim3(KVDIM / 128, NTOK / 128), 256>>>(h, lkw, k, nullptr, NTOK, KVDIM, DMODEL);
        sgemm_kernel<0><<<dim3(KVDIM / 128, NTOK / 128), 256>>>(h, lvw, v, nullptr, NTOK, KVDIM, DMODEL);
        rope_kernel<<<NTOK * NHEAD * 32 / 256, 256>>>(q, NHEAD);
        rope_kernel<<<NTOK * NKV * 32 / 256, 256>>>(k, NKV);
        attn_kernel<<<dim3(SEQ / 64, 2 * NHEAD), 256>>>(q, k, v, o);
        sgemm_kernel<1><<<dim3(DMODEL / 128, NTOK / 128), 256>>>(o, low, x, x, NTOK, DMODEL, DMODEL);
        rmsnorm_kernel<<<NTOK, 256>>>(x, ln2 + l * DMODEL, h);
        sgemm_kernel<2><<<dim3(FFN / 128, NTOK / 128), 256>>>(h, lw1, gate, nullptr, NTOK, FFN, DMODEL);
        sgemm_kernel<3><<<dim3(FFN / 128, NTOK / 128), 256>>>(h, lw3, up, gate, NTOK, FFN, DMODEL);
        sgemm_kernel<1><<<dim3(DMODEL / 128, NTOK / 128), 256>>>(up, lw2, x, x, NTOK, DMODEL, FFN);
    }

    rmsnorm_kernel<<<NTOK, 256>>>(x, lnf, h);
    sgemm_kernel<0><<<dim3(VOCAB / 128, NTOK / 128), 256>>>(h, emb, out, nullptr, NTOK, VOCAB, DMODEL);
}

// round 4
// speedup vs baseline: 2.3014x; 2.3014x over previous
#include <cuda_runtime.h>
#include <cuda_bf16.h>
#include <stdint.h>
#include <math.h>

#define NTOK 2048
#define DMODEL 1024
#define NHEAD 16
#define NKV 4
#define HEADDIM 64
#define FFN 4096
#define VOCAB 32000
#define NLAYER 4
#define SEQ 1024
#define KVDIM (NKV * HEADDIM)   // 256

#define EMB_N (VOCAB * DMODEL)
#define QW_N (NLAYER * DMODEL * DMODEL)
#define KW_N (NLAYER * KVDIM * DMODEL)
#define W1_N (NLAYER * FFN * DMODEL)

// ---------------- scratch (device globals; no runtime allocation) ----------------
__device__ float g_x[NTOK * DMODEL];
__device__ float g_q[NTOK * DMODEL];
__device__ float g_k[NTOK * KVDIM];
__device__ float g_v[NTOK * KVDIM];
__device__ float g_gate[NTOK * FFN];

__device__ __nv_bfloat16 g_h_h[NTOK * DMODEL], g_h_l[NTOK * DMODEL];
__device__ __nv_bfloat16 g_o_h[NTOK * DMODEL], g_o_l[NTOK * DMODEL];
__device__ __nv_bfloat16 g_up_h[NTOK * FFN],  g_up_l[NTOK * FFN];

__device__ __nv_bfloat16 s_emb_h[EMB_N], s_emb_l[EMB_N];
__device__ __nv_bfloat16 s_qw_h[QW_N],  s_qw_l[QW_N];
__device__ __nv_bfloat16 s_kw_h[KW_N],  s_kw_l[KW_N];
__device__ __nv_bfloat16 s_vw_h[KW_N],  s_vw_l[KW_N];
__device__ __nv_bfloat16 s_ow_h[QW_N],  s_ow_l[QW_N];
__device__ __nv_bfloat16 s_w1_h[W1_N],  s_w1_l[W1_N];
__device__ __nv_bfloat16 s_w2_h[W1_N],  s_w2_l[W1_N];
__device__ __nv_bfloat16 s_w3_h[W1_N],  s_w3_l[W1_N];

// ---------------- helpers ----------------
__device__ __forceinline__ void cpa16(uint32_t s, const void* g) {
    asm volatile("cp.async.cg.shared.global [%0], [%1], 16;" :: "r"(s), "l"(g));
}
__device__ __forceinline__ void split2(float x, __nv_bfloat16& h, __nv_bfloat16& l) {
    h = __float2bfloat16(x);
    l = __float2bfloat16(x - __bfloat162float(h));
}
__device__ __forceinline__ void mma_bf16(float* d, const uint32_t* a, const uint32_t* b) {
    asm volatile(
        "mma.sync.aligned.m16n8k16.row.col.f32.bf16.bf16.f32 "
        "{%0,%1,%2,%3},{%4,%5,%6,%7},{%8,%9},{%0,%1,%2,%3};"
        : "+f"(d[0]), "+f"(d[1]), "+f"(d[2]), "+f"(d[3])
        : "r"(a[0]), "r"(a[1]), "r"(a[2]), "r"(a[3]), "r"(b[0]), "r"(b[1]));
}

// ---------------- pre-pass: fp32 -> bf16 hi/lo planes ----------------
__global__ void split_kernel(const float* __restrict__ src,
                             __nv_bfloat16* __restrict__ hi,
                             __nv_bfloat16* __restrict__ lo) {
    int idx = blockIdx.x * 256 + threadIdx.x;   // float4 index
    float4 v = ((const float4*)src)[idx];
    __nv_bfloat16 h0, h1, h2, h3, l0, l1, l2, l3;
    split2(v.x, h0, l0);
    split2(v.y, h1, l1);
    split2(v.z, h2, l2);
    split2(v.w, h3, l3);
    __nv_bfloat162* hp = (__nv_bfloat162*)hi;
    __nv_bfloat162* lp = (__nv_bfloat162*)lo;
    hp[idx * 2]     = __nv_bfloat162{h0, h1};
    hp[idx * 2 + 1] = __nv_bfloat162{h2, h3};
    lp[idx * 2]     = __nv_bfloat162{l0, l1};
    lp[idx * 2 + 1] = __nv_bfloat162{l2, l3};
}

// ---------------- embedding gather ----------------
__global__ void embed_kernel(const int* __restrict__ ids,
                             const float* __restrict__ emb,
                             float* __restrict__ x) {
    int idx = blockIdx.x * 256 + threadIdx.x;
    int n = idx >> 8;
    int c = idx & 255;
    const float4* e4 = (const float4*)emb;
    ((float4*)x)[idx] = e4[(size_t)ids[n] * 256 + c];
}

// ---------------- RMSNorm -> bf16 hi/lo planes ----------------
__global__ void rmsnorm_split_kernel(const float* __restrict__ x,
                                     const float* __restrict__ w,
                                     __nv_bfloat16* __restrict__ hi,
                                     __nv_bfloat16* __restrict__ lo) {
    int n = blockIdx.x;
    int tid = threadIdx.x;
    const float4* xr = (const float4*)(x + (size_t)n * DMODEL);
    float4 v = xr[tid];
    float ss = v.x * v.x + v.y * v.y + v.z * v.z + v.w * v.w;
#pragma unroll
    for (int o = 16; o > 0; o >>= 1) ss += __shfl_xor_sync(0xffffffffu, ss, o);
    __shared__ float red[8];
    if ((tid & 31) == 0) red[tid >> 5] = ss;
    __syncthreads();
    float tot = 0.f;
#pragma unroll
    for (int i = 0; i < 8; i++) tot += red[i];
    float r = rsqrtf(tot * (1.0f / DMODEL) + 1e-6f);
    float4 wv = ((const float4*)w)[tid];
    float o0 = wv.x * v.x * r, o1 = wv.y * v.y * r, o2 = wv.z * v.z * r, o3 = wv.w * v.w * r;
    __nv_bfloat16 h0, h1, h2, h3, l0, l1, l2, l3;
    split2(o0, h0, l0); split2(o1, h1, l1); split2(o2, h2, l2); split2(o3, h3, l3);
    __nv_bfloat162* hp = (__nv_bfloat162*)(hi + (size_t)n * DMODEL);
    __nv_bfloat162* lp = (__nv_bfloat162*)(lo + (size_t)n * DMODEL);
    hp[tid * 2]     = __nv_bfloat162{h0, h1};
    hp[tid * 2 + 1] = __nv_bfloat162{h2, h3};
    lp[tid * 2]     = __nv_bfloat162{l0, l1};
    lp[tid * 2 + 1] = __nv_bfloat162{l2, l3};
}

// ---------------- RoPE (in-place, fp32) ----------------
__global__ void rope_kernel(float* __restrict__ buf, int nheads) {
    int idx = blockIdx.x * blockDim.x + threadIdx.x;
    int i = idx & 31;
    int hn = idx >> 5;
    int head = hn % nheads;
    int n = hn / nheads;
    int t = n & (SEQ - 1);
    float inv = 1.0f / powf(10000.0f, (float)i * (1.0f / 32.0f));
    float ang = (float)t * inv;
    float s, c;
    sincosf(ang, &s, &c);
    float* p = buf + (size_t)n * nheads * HEADDIM + head * HEADDIM + i;
    float x1 = p[0], x2 = p[32];
    p[0]  = x1 * c - x2 * s;
    p[32] = x2 * c + x1 * s;
}

// ---------------- 3xBF16 tensor-core GEMM ----------------
// C[N,M] = A[N,K] * W[M,K]^T, A/W given as bf16 hi/lo planes.
// EPI: 0 store fp32, 1 residual add, 2 SiLU, 3 (acc*aux) -> split planes Phi/Plo
#define BK 32
#define SP 40                 // bf16 per smem row (32 data + 8 pad)
#define SP32 20               // in b32 units
#define PLANE (128 * SP)      // 5120 bf16
#define STAGE (4 * PLANE)     // 20480 bf16 per stage
#define GEMM_SMEM (2 * STAGE * 2)  // 81920 bytes

template <int EPI>
__global__ __launch_bounds__(256) void gemm_bf3(
    const __nv_bfloat16* __restrict__ Ahi, const __nv_bfloat16* __restrict__ Alo,
    const __nv_bfloat16* __restrict__ Whi, const __nv_bfloat16* __restrict__ Wlo,
    float* __restrict__ C, const float* __restrict__ aux,
    __nv_bfloat16* __restrict__ Phi, __nv_bfloat16* __restrict__ Plo,
    int K, int M) {
    extern __shared__ __nv_bfloat16 smb[];
    int tid = threadIdx.x, lane = tid & 31, warp = tid >> 5;
    int wm = warp >> 2, wn = warp & 3;
    int m0 = blockIdx.x * 128, n0 = blockIdx.y * 128;

    const __nv_bfloat16* Ah = Ahi + (size_t)n0 * K;
    const __nv_bfloat16* Al = Alo + (size_t)n0 * K;
    const __nv_bfloat16* Wh = Whi + (size_t)m0 * K;
    const __nv_bfloat16* Wl = Wlo + (size_t)m0 * K;

    float acc[4][4][4] = {};

    auto load_stage = [&](int s, int kt) {
        __nv_bfloat16* base = smb + s * STAGE;
        const __nv_bfloat16* gp[4] = {Ah + kt, Al + kt, Wh + kt, Wl + kt};
#pragma unroll
        for (int pl = 0; pl < 4; pl++) {
#pragma unroll
            for (int hf = 0; hf < 2; hf++) {
                int row = hf * 64 + (tid >> 2);
                int seg = tid & 3;
                cpa16((uint32_t)__cvta_generic_to_shared(base + pl * PLANE + row * SP + seg * 8),
                      gp[pl] + (size_t)row * K + seg * 8);
            }
        }
        asm volatile("cp.async.commit_group;" ::: "memory");
    };

    load_stage(0, 0);
    int KT = K >> 5;
    int r = lane >> 2, c = lane & 3;
    for (int kt = 0; kt < KT; kt++) {
        asm volatile("cp.async.wait_group 0;" ::: "memory");
        __syncthreads();
        if (kt + 1 < KT) load_stage((kt + 1) & 1, (kt + 1) * BK);
        const __nv_bfloat16* cb = smb + (kt & 1) * STAGE;
        const uint32_t* aH = (const uint32_t*)(cb);
        const uint32_t* aL = (const uint32_t*)(cb + PLANE);
        const uint32_t* wH = (const uint32_t*)(cb + 2 * PLANE);
        const uint32_t* wL = (const uint32_t*)(cb + 3 * PLANE);
#pragma unroll
        for (int ks = 0; ks < 2; ks++) {
            int kb = ks * 8 + c;
            uint32_t ah[4][4], bh[4][2], bl[4][2];
#pragma unroll
            for (int i = 0; i < 4; i++) {
                int m = wm * 64 + i * 16 + r;
                ah[i][0] = aH[m * SP32 + kb];
                ah[i][1] = aH[(m + 8) * SP32 + kb];
                ah[i][2] = aH[m * SP32 + kb + 4];
                ah[i][3] = aH[(m + 8) * SP32 + kb + 4];
            }
#pragma unroll
            for (int j = 0; j < 4; j++) {
                int n = wn * 32 + j * 8 + r;
                bh[j][0] = wH[n * SP32 + kb];
                bh[j][1] = wH[n * SP32 + kb + 4];
                bl[j][0] = wL[n * SP32 + kb];
                bl[j][1] = wL[n * SP32 + kb + 4];
            }
#pragma unroll
            for (int i = 0; i < 4; i++)
#pragma unroll
                for (int j = 0; j < 4; j++) {
                    mma_bf16(acc[i][j], ah[i], bh[j]);
                    mma_bf16(acc[i][j], ah[i], bl[j]);
                }
            uint32_t al[4][4];
#pragma unroll
            for (int i = 0; i < 4; i++) {
                int m = wm * 64 + i * 16 + r;
                al[i][0] = aL[m * SP32 + kb];
                al[i][1] = aL[(m + 8) * SP32 + kb];
                al[i][2] = aL[m * SP32 + kb + 4];
                al[i][3] = aL[(m + 8) * SP32 + kb + 4];
            }
#pragma unroll
            for (int i = 0; i < 4; i++)
#pragma unroll
                for (int j = 0; j < 4; j++)
                    mma_bf16(acc[i][j], al[i], bh[j]);
        }
        __syncthreads();
    }

    // epilogue
    int rr = lane >> 2, cc = (lane & 3) * 2;
#pragma unroll
    for (int i = 0; i < 4; i++) {
#pragma unroll
        for (int half = 0; half < 2; half++) {
            int grow = n0 + wm * 64 + i * 16 + rr + half * 8;
#pragma unroll
            for (int j = 0; j < 4; j++) {
                int gcol = m0 + wn * 32 + j * 8 + cc;
                size_t off = (size_t)grow * M + gcol;
                float2 v = make_float2(acc[i][j][half * 2], acc[i][j][half * 2 + 1]);
                if (EPI == 1) {
                    float2 rv = *(const float2*)(aux + off);
                    v.x += rv.x; v.y += rv.y;
                } else if (EPI == 2) {
                    v.x = v.x / (1.0f + __expf(-v.x));
                    v.y = v.y / (1.0f + __expf(-v.y));
                } else if (EPI == 3) {
                    float2 rv = *(const float2*)(aux + off);
                    v.x *= rv.x; v.y *= rv.y;
                    __nv_bfloat16 h0, h1, l0, l1;
                    split2(v.x, h0, l0);
                    split2(v.y, h1, l1);
                    *(__nv_bfloat162*)(Phi + off) = __nv_bfloat162{h0, h1};
                    *(__nv_bfloat162*)(Plo + off) = __nv_bfloat162{l0, l1};
                }
                if (EPI != 3) *(float2*)(C + off) = v;
            }
        }
    }
}

// ---------------- causal flash attention (fp32, GQA) -> bf16 hi/lo output ----------------
__global__ __launch_bounds__(256) void attn_kernel(
    const float* __restrict__ Q, const float* __restrict__ K,
    const float* __restrict__ V,
    __nv_bfloat16* __restrict__ Ohi, __nv_bfloat16* __restrict__ Olo) {
    __shared__ float Qs[64][64];
    __shared__ float Ks[32][68];
    __shared__ float Vs[32][64];
    __shared__ float Ps[64][33];
    int bh = blockIdx.y;
    int b = bh >> 4;
    int h = bh & 15;
    int kvh = h >> 2;
    int q0 = blockIdx.x * 64;
    int tid = threadIdx.x;
    int lane = tid & 31, warp = tid >> 5;
    const float scale = 0.125f;

    const float* Qbase = Q + ((size_t)(b * SEQ + q0)) * DMODEL + h * HEADDIM;
    for (int i = tid; i < 64 * 16; i += 256) {
        int row = i >> 4, c = (i & 15) * 4;
        float4 v = *(const float4*)(Qbase + (size_t)row * DMODEL + c);
        Qs[row][c + 0] = v.x * scale;
        Qs[row][c + 1] = v.y * scale;
        Qs[row][c + 2] = v.z * scale;
        Qs[row][c + 3] = v.w * scale;
    }

    float m[8], l[8], acc0[8], acc1[8];
#pragma unroll
    for (int r = 0; r < 8; r++) { m[r] = -1e30f; l[r] = 0.f; acc0[r] = 0.f; acc1[r] = 0.f; }

    int kend = q0 + 64;
    for (int kc = 0; kc < kend; kc += 32) {
        __syncthreads();
        const float* Kbase = K + ((size_t)(b * SEQ + kc)) * KVDIM + kvh * HEADDIM;
        const float* Vbase = V + ((size_t)(b * SEQ + kc)) * KVDIM + kvh * HEADDIM;
        for (int i = tid; i < 32 * 16; i += 256) {
            int row = i >> 4, c = (i & 15) * 4;
            float4 kv = *(const float4*)(Kbase + (size_t)row * KVDIM + c);
            Ks[row][c + 0] = kv.x;
            Ks[row][c + 1] = kv.y;
            Ks[row][c + 2] = kv.z;
            Ks[row][c + 3] = kv.w;
            float4 vv = *(const float4*)(Vbase + (size_t)row * KVDIM + c);
            *(float4*)&Vs[row][c] = vv;
        }
        __syncthreads();

        float s[8] = {0.f, 0.f, 0.f, 0.f, 0.f, 0.f, 0.f, 0.f};
#pragma unroll
        for (int d4 = 0; d4 < 16; d4++) {
            float4 kv = *(const float4*)&Ks[lane][d4 * 4];
#pragma unroll
            for (int r = 0; r < 8; r++) {
                float4 qv = *(const float4*)&Qs[warp * 8 + r][d4 * 4];
                s[r] += qv.x * kv.x + qv.y * kv.y + qv.z * kv.z + qv.w * kv.w;
            }
        }
        int key = kc + lane;
#pragma unroll
        for (int r = 0; r < 8; r++) {
            int qrow = q0 + warp * 8 + r;
            float sv = (key <= qrow) ? s[r] : -1e30f;
            float mx = sv;
#pragma unroll
            for (int o = 16; o > 0; o >>= 1) mx = fmaxf(mx, __shfl_xor_sync(0xffffffffu, mx, o));
            float mn = fmaxf(m[r], mx);
            float p = __expf(sv - mn);
            float cor = __expf(m[r] - mn);
            float ps = p;
#pragma unroll
            for (int o = 16; o > 0; o >>= 1) ps += __shfl_xor_sync(0xffffffffu, ps, o);
            l[r] = l[r] * cor + ps;
            acc0[r] *= cor;
            acc1[r] *= cor;
            m[r] = mn;
            Ps[warp * 8 + r][lane] = p;
        }
        __syncwarp();
#pragma unroll 4
        for (int j = 0; j < 32; j++) {
            float v0 = Vs[j][lane];
            float v1 = Vs[j][lane + 32];
#pragma unroll
            for (int r = 0; r < 8; r++) {
                float p = Ps[warp * 8 + r][j];
                acc0[r] += p * v0;
                acc1[r] += p * v1;
            }
        }
    }

    size_t obase = ((size_t)(b * SEQ + q0)) * DMODEL + h * HEADDIM;
#pragma unroll
    for (int r = 0; r < 8; r++) {
        int row = warp * 8 + r;
        float inv = 1.0f / l[r];
        float v0 = acc0[r] * inv, v1 = acc1[r] * inv;
        __nv_bfloat16 h0, h1, l0, l1;
        split2(v0, h0, l0);
        split2(v1, h1, l1);
        size_t o0 = obase + (size_t)row * DMODEL + lane;
        Ohi[o0] = h0;  Olo[o0] = l0;
        Ohi[o0 + 32] = h1;  Olo[o0 + 32] = l1;
    }
}

// ---------------- host orchestration ----------------
extern "C" void kernel_launch(void* const* d_in, const int* in_sizes, int n_in,
                              void* d_out, int out_size) {
    const int*   ids = (const int*)d_in[0];
    const float* emb = (const float*)d_in[1];
    const float* ln1 = (const float*)d_in[2];
    const float* qw  = (const float*)d_in[3];
    const float* kw  = (const float*)d_in[4];
    const float* vw  = (const float*)d_in[5];
    const float* ow  = (const float*)d_in[6];
    const float* ln2 = (const float*)d_in[7];
    const float* w1  = (const float*)d_in[8];
    const float* w2  = (const float*)d_in[9];
    const float* w3  = (const float*)d_in[10];
    const float* lnf = (const float*)d_in[11];
    float* out = (float*)d_out;

    float *x, *q, *k, *v, *gate;
    __nv_bfloat16 *hh, *hl, *oh, *ol, *uph, *upl;
    __nv_bfloat16 *embh, *embl, *qwh, *qwl, *kwh, *kwl, *vwh, *vwl, *owh, *owl;
    __nv_bfloat16 *w1h, *w1l, *w2h, *w2l, *w3h, *w3l;
    cudaGetSymbolAddress((void**)&x, g_x);
    cudaGetSymbolAddress((void**)&q, g_q);
    cudaGetSymbolAddress((void**)&k, g_k);
    cudaGetSymbolAddress((void**)&v, g_v);
    cudaGetSymbolAddress((void**)&gate, g_gate);
    cudaGetSymbolAddress((void**)&hh, g_h_h);
    cudaGetSymbolAddress((void**)&hl, g_h_l);
    cudaGetSymbolAddress((void**)&oh, g_o_h);
    cudaGetSymbolAddress((void**)&ol, g_o_l);
    cudaGetSymbolAddress((void**)&uph, g_up_h);
    cudaGetSymbolAddress((void**)&upl, g_up_l);
    cudaGetSymbolAddress((void**)&embh, s_emb_h);
    cudaGetSymbolAddress((void**)&embl, s_emb_l);
    cudaGetSymbolAddress((void**)&qwh, s_qw_h);
    cudaGetSymbolAddress((void**)&qwl, s_qw_l);
    cudaGetSymbolAddress((void**)&kwh, s_kw_h);
    cudaGetSymbolAddress((void**)&kwl, s_kw_l);
    cudaGetSymbolAddress((void**)&vwh, s_vw_h);
    cudaGetSymbolAddress((void**)&vwl, s_vw_l);
    cudaGetSymbolAddress((void**)&owh, s_ow_h);
    cudaGetSymbolAddress((void**)&owl, s_ow_l);
    cudaGetSymbolAddress((void**)&w1h, s_w1_h);
    cudaGetSymbolAddress((void**)&w1l, s_w1_l);
    cudaGetSymbolAddress((void**)&w2h, s_w2_h);
    cudaGetSymbolAddress((void**)&w2l, s_w2_l);
    cudaGetSymbolAddress((void**)&w3h, s_w3_h);
    cudaGetSymbolAddress((void**)&w3l, s_w3_l);

    cudaFuncSetAttribute(gemm_bf3<0>, cudaFuncAttributeMaxDynamicSharedMemorySize, GEMM_SMEM);
    cudaFuncSetAttribute(gemm_bf3<1>, cudaFuncAttributeMaxDynamicSharedMemorySize, GEMM_SMEM);
    cudaFuncSetAttribute(gemm_bf3<2>, cudaFuncAttributeMaxDynamicSharedMemorySize, GEMM_SMEM);
    cudaFuncSetAttribute(gemm_bf3<3>, cudaFuncAttributeMaxDynamicSharedMemorySize, GEMM_SMEM);

    // pre-pass: split weights into bf16 hi/lo planes
    split_kernel<<<EMB_N / 1024, 256>>>(emb, embh, embl);
    split_kernel<<<QW_N / 1024, 256>>>(qw, qwh, qwl);
    split_kernel<<<KW_N / 1024, 256>>>(kw, kwh, kwl);
    split_kernel<<<KW_N / 1024, 256>>>(vw, vwh, vwl);
    split_kernel<<<QW_N / 1024, 256>>>(ow, owh, owl);
    split_kernel<<<W1_N / 1024, 256>>>(w1, w1h, w1l);
    split_kernel<<<W1_N / 1024, 256>>>(w2, w2h, w2l);
    split_kernel<<<W1_N / 1024, 256>>>(w3, w3h, w3l);

    embed_kernel<<<NTOK, 256>>>(ids, emb, x);

    for (int l = 0; l < NLAYER; l++) {
        size_t qo = (size_t)l * DMODEL * DMODEL;
        size_t ko = (size_t)l * KVDIM * DMODEL;
        size_t fo = (size_t)l * FFN * DMODEL;

        rmsnorm_split_kernel<<<NTOK, 256>>>(x, ln1 + l * DMODEL, hh, hl);
        gemm_bf3<0><<<dim3(DMODEL / 128, 16), 256, GEMM_SMEM>>>(
            hh, hl, qwh + qo, qwl + qo, q, nullptr, nullptr, nullptr, DMODEL, DMODEL);
        gemm_bf3<0><<<dim3(KVDIM / 128, 16), 256, GEMM_SMEM>>>(
            hh, hl, kwh + ko, kwl + ko, k, nullptr, nullptr, nullptr, DMODEL, KVDIM);
        gemm_bf3<0><<<dim3(KVDIM / 128, 16), 256, GEMM_SMEM>>>(
            hh, hl, vwh + ko, vwl + ko, v, nullptr, nullptr, nullptr, DMODEL, KVDIM);
        rope_kernel<<<NTOK * NHEAD * 32 / 256, 256>>>(q, NHEAD);
        rope_kernel<<<NTOK * NKV * 32 / 256, 256>>>(k, NKV);
        attn_kernel<<<dim3(SEQ / 64, 2 * NHEAD), 256>>>(q, k, v, oh, ol);
        gemm_bf3<1><<<dim3(DMODEL / 128, 16), 256, GEMM_SMEM>>>(
            oh, ol, owh + qo, owl + qo, x, x, nullptr, nullptr, DMODEL, DMODEL);
        rmsnorm_split_kernel<<<NTOK, 256>>>(x, ln2 + l * DMODEL, hh, hl);
        gemm_bf3<2><<<dim3(FFN / 128, 16), 256, GEMM_SMEM>>>(
            hh, hl, w1h + fo, w1l + fo, gate, nullptr, nullptr, nullptr, DMODEL, FFN);
        gemm_bf3<3><<<dim3(FFN / 128, 16), 256, GEMM_SMEM>>>(
            hh, hl, w3h + fo, w3l + fo, nullptr, gate, uph, upl, DMODEL, FFN);
        gemm_bf3<1><<<dim3(DMODEL / 128, 16), 256, GEMM_SMEM>>>(
            uph, upl, w2h + fo, w2l + fo, x, x, nullptr, nullptr, FFN, DMODEL);
    }

    rmsnorm_split_kernel<<<NTOK, 256>>>(x, lnf, hh, hl);
    gemm_bf3<0><<<dim3(VOCAB / 128, 16), 256, GEMM_SMEM>>>(
        hh, hl, embh, embl, out, nullptr, nullptr, nullptr, DMODEL, VOCAB);
}